// round 15
// baseline (speedup 1.0000x reference)
#include <cuda_runtime.h>
#include <cuda_bf16.h>

// Inputs (metadata order):
//   d_in[0] input_values   float32 [1024]
//   d_in[1] weight_matrix  float32 [16384*16384] row-major
//   d_in[2] biases         float32 [16384]
//   d_in[3] act_ids        int32   [16384]   0=identity 1=relu 2=softsign
//   d_in[4] input_indices  int32   [1024]
//   d_in[5] output_indices int32   [256]
// Output: float32 [256]
//
// out[o] = act( sum_i in_vals[i] * W[in_idx[i], out_idx[o]] + bias[out_idx[o]] )
//
// FINAL (locked, best warm 6.656us AND best cold 8.896us of the session):
// single launch, one CTA per output, BLOCK=512 (occ ~39%, 16 warps/SM hiding
// scattered-load latency), vectorized int2/float2 metadata loads, 32-bit
// address math (row*16384 + j < 2^28), 2 independent W gathers per thread,
// 16-warp shuffle+smem reduction, finalize loads issued after the barrier
// (off the block makespan; hoisting them regressed in R12). Multi-node graphs
// (+~2us/node) and cross-CTA combine protocols (atomics/fences) measurably
// regress and are intentionally absent.

#define BLOCK 512

__global__ void __launch_bounds__(BLOCK, 2)
custom_network_kernel(const float* __restrict__ in_vals,
                      const float* __restrict__ W,
                      const float* __restrict__ bias,
                      const int*   __restrict__ act_ids,
                      const int*   __restrict__ in_idx,
                      const int*   __restrict__ out_idx,
                      float*       __restrict__ out,
                      int n_in, int N)
{
    const int t = threadIdx.x;
    const int j = __ldg(&out_idx[blockIdx.x]);   // uniform per CTA

    float p = 0.0f;

    if ((n_in & (2 * BLOCK - 1)) == 0) {
        // fast path: one int2 + one float2 metadata load, 2 W-gathers per tile
        const int2*   idx2 = (const int2*)in_idx;
        const float2* val2 = (const float2*)in_vals;
        const int tiles = n_in / (2 * BLOCK);    // 1 for n_in=1024
        for (int ti = 0; ti < tiles; ti++) {
            const int base = ti * BLOCK + t;
            const int2   r2 = __ldg(&idx2[base]);
            const float2 v2 = __ldg(&val2[base]);
            // 2 independent scattered loads, 32-bit addressing
            const float w0 = __ldg(&W[r2.x * N + j]);
            const float w1 = __ldg(&W[r2.y * N + j]);
            p += v2.x * w0 + v2.y * w1;
        }
    } else {
        for (int i = t; i < n_in; i += BLOCK) {
            const int r = __ldg(&in_idx[i]);
            p += __ldg(&in_vals[i]) * __ldg(&W[r * N + j]);
        }
    }

    // warp reduce (16 warps) then cross-warp combine
    #pragma unroll
    for (int off = 16; off > 0; off >>= 1)
        p += __shfl_xor_sync(0xFFFFFFFFu, p, off);

    __shared__ float sm[BLOCK / 32];
    const int lane = t & 31;
    const int wid  = t >> 5;
    if (lane == 0) sm[wid] = p;
    __syncthreads();

    if (wid == 0) {
        float v = (lane < BLOCK / 32) ? sm[lane] : 0.0f;
        #pragma unroll
        for (int off = 8; off > 0; off >>= 1)
            v += __shfl_xor_sync(0xFFFFFFFFu, v, off);

        if (lane == 0) {
            const float total = v + __ldg(&bias[j]);
            const int   a     = __ldg(&act_ids[j]);
            const float relu  = fmaxf(total, 0.0f);
            const float ssign = total / (1.0f + fabsf(total));
            out[blockIdx.x] = (a == 1) ? relu : ((a == 2) ? ssign : total);
        }
    }
}

extern "C" void kernel_launch(void* const* d_in, const int* in_sizes, int n_in_args,
                              void* d_out, int out_size)
{
    const float* in_vals = (const float*)d_in[0];
    const float* W       = (const float*)d_in[1];
    const float* bias    = (const float*)d_in[2];
    const int*   act_ids = (const int*)  d_in[3];
    const int*   in_idx  = (const int*)  d_in[4];
    const int*   out_idx = (const int*)  d_in[5];
    float*       out     = (float*)      d_out;

    const int n_in = in_sizes[0];   // 1024
    const int N    = in_sizes[2];   // 16384 (bias length)

    custom_network_kernel<<<out_size, BLOCK>>>(
        in_vals, W, bias, act_ids, in_idx, out_idx, out, n_in, N);
}

// round 16
// speedup vs baseline: 1.0386x; 1.0386x over previous
#include <cuda_runtime.h>
#include <cuda_bf16.h>

// Inputs (metadata order):
//   d_in[0] input_values   float32 [1024]
//   d_in[1] weight_matrix  float32 [16384*16384] row-major
//   d_in[2] biases         float32 [16384]
//   d_in[3] act_ids        int32   [16384]   0=identity 1=relu 2=softsign
//   d_in[4] input_indices  int32   [1024]
//   d_in[5] output_indices int32   [256]
// Output: float32 [256]
//
// out[o] = act( sum_i in_vals[i] * W[in_idx[i], out_idx[o]] + bias[out_idx[o]] )
//
// FINAL — converged design (best warm 6.656us and best cold 8.896us of the
// session; 3 identical-source runs bound the bench noise at roughly +/-1us):
//  * sparse-aware gather: only the 256 needed columns x 1024 active rows of W
//    are touched (~27MB of DRAM lines vs 1GB for the dense GEMV, ~40x less).
//  * ONE kernel node (each extra graph node costs ~2us: R2), one CTA per
//    output, BLOCK=512 -> ~39% occupancy, 16 warps/SM hiding the fully
//    scattered 4B load latency.
//  * one int2 + one float2 metadata load per thread, then 2 independent W
//    gathers with 32-bit address math (row*16384 + j < 2^28).
//  * 16-warp shuffle + smem reduction; bias/act loads issued by warp 0 AFTER
//    the barrier (off the block makespan; hoisting them regressed: R12).
//  * no cross-CTA combine protocols (atomics/fences regress: R3, R11).

#define BLOCK 512

__global__ void __launch_bounds__(BLOCK, 2)
custom_network_kernel(const float* __restrict__ in_vals,
                      const float* __restrict__ W,
                      const float* __restrict__ bias,
                      const int*   __restrict__ act_ids,
                      const int*   __restrict__ in_idx,
                      const int*   __restrict__ out_idx,
                      float*       __restrict__ out,
                      int n_in, int N)
{
    const int t = threadIdx.x;
    const int j = __ldg(&out_idx[blockIdx.x]);   // uniform per CTA

    float p = 0.0f;

    if ((n_in & (2 * BLOCK - 1)) == 0) {
        // fast path: one int2 + one float2 metadata load, 2 W-gathers per tile
        const int2*   idx2 = (const int2*)in_idx;
        const float2* val2 = (const float2*)in_vals;
        const int tiles = n_in / (2 * BLOCK);    // 1 for n_in=1024
        for (int ti = 0; ti < tiles; ti++) {
            const int base = ti * BLOCK + t;
            const int2   r2 = __ldg(&idx2[base]);
            const float2 v2 = __ldg(&val2[base]);
            // 2 independent scattered loads, 32-bit addressing
            const float w0 = __ldg(&W[r2.x * N + j]);
            const float w1 = __ldg(&W[r2.y * N + j]);
            p += v2.x * w0 + v2.y * w1;
        }
    } else {
        // generic path for arbitrary n_in
        for (int i = t; i < n_in; i += BLOCK) {
            const int r = __ldg(&in_idx[i]);
            p += __ldg(&in_vals[i]) * __ldg(&W[r * N + j]);
        }
    }

    // warp reduce (16 warps) then cross-warp combine
    #pragma unroll
    for (int off = 16; off > 0; off >>= 1)
        p += __shfl_xor_sync(0xFFFFFFFFu, p, off);

    __shared__ float sm[BLOCK / 32];
    const int lane = t & 31;
    const int wid  = t >> 5;
    if (lane == 0) sm[wid] = p;
    __syncthreads();

    if (wid == 0) {
        float v = (lane < BLOCK / 32) ? sm[lane] : 0.0f;
        #pragma unroll
        for (int off = 8; off > 0; off >>= 1)
            v += __shfl_xor_sync(0xFFFFFFFFu, v, off);

        if (lane == 0) {
            const float total = v + __ldg(&bias[j]);
            const int   a     = __ldg(&act_ids[j]);
            const float relu  = fmaxf(total, 0.0f);
            const float ssign = total / (1.0f + fabsf(total));
            out[blockIdx.x] = (a == 1) ? relu : ((a == 2) ? ssign : total);
        }
    }
}

extern "C" void kernel_launch(void* const* d_in, const int* in_sizes, int n_in_args,
                              void* d_out, int out_size)
{
    const float* in_vals = (const float*)d_in[0];
    const float* W       = (const float*)d_in[1];
    const float* bias    = (const float*)d_in[2];
    const int*   act_ids = (const int*)  d_in[3];
    const int*   in_idx  = (const int*)  d_in[4];
    const int*   out_idx = (const int*)  d_in[5];
    float*       out     = (float*)      d_out;

    const int n_in = in_sizes[0];   // 1024
    const int N    = in_sizes[2];   // 16384 (bias length)

    custom_network_kernel<<<out_size, BLOCK>>>(
        in_vals, W, bias, act_ids, in_idx, out_idx, out, n_in, N);
}